// round 5
// baseline (speedup 1.0000x reference)
#include <cuda_runtime.h>
#include <cuda_bf16.h>

// Fixed shapes: B=1, N=1000, T=256, D=512, M=258, NUM=10
// out row = 6*512 + 10 = 3082 floats (12328 B -> 16B-aligned only for even n)
#define N_CAND 1000
#define T_DIM 256
#define D_DIM 512
#define M_DIM 258
#define NUMF 10
#define ROW_OUT (6 * D_DIM + NUMF)   // 3082

// One block per candidate, 256 threads.
// Threads split into two halves of 128 lanes; each half copies 3 of the 6
// 512-float sections with float4 loads (source rows are 2048B-aligned).
//   half 0: sections 0 (blo[c1]), 2 (blo[c4]), 4 (att[c0+2])
//   half 1: sections 1 (blo[c2]), 3 (blo[c5]), 5 (att[c3+2])
// Stores: float4 when the output row is 16B-aligned (even n), else 2x float2.
__global__ __launch_bounds__(256) void feature_gather_kernel(
    const int* __restrict__ cand,        // [N,6]
    const float* __restrict__ num,       // [N,10]
    const float* __restrict__ blo,       // [N,T,D]
    const float* __restrict__ att,       // [N,M,D]
    float* __restrict__ out)             // [N,3082]
{
    const int n = blockIdx.x;
    const int t = threadIdx.x;
    const int half = t >> 7;       // 0 or 1
    const int lane = t & 127;      // 0..127  (float4 lane within a section)

    // Candidate indices: 24B row, always 8B-aligned -> three int2 loads.
    const int2* cp = (const int2*)(cand + n * 6);
    const int2 p01 = cp[0];        // c0, c1
    const int2 p23 = cp[1];        // c2, c3
    const int2 p45 = cp[2];        // c4, c5

    const float4* b4 = (const float4*)(blo + (size_t)n * T_DIM * D_DIM);
    const float4* a4 = (const float4*)(att + (size_t)n * M_DIM * D_DIM);
    const int R4 = D_DIM / 4;      // 128 float4 per row

    const int rowA = half ? p23.x : p01.y;          // c2 : c1      (blo)
    const int rowB = half ? p45.y : p45.x;          // c5 : c4      (blo)
    const int rowC = (half ? p23.y : p01.x) + 2;    // c3+2 : c0+2  (att)

    // Issue all three 16B loads before any store (MLP=3).
    const float4 vA = b4[(size_t)rowA * R4 + lane];
    const float4 vB = b4[(size_t)rowB * R4 + lane];
    const float4 vC = a4[(size_t)rowC * R4 + lane];

    float* outRow = out + (size_t)n * ROW_OUT;
    // Destination section ids: sA = half, sB = half+2, sC = half+4.
    if ((n & 1) == 0) {
        float4* o4 = (float4*)outRow;                 // 16B-aligned row
        o4[(half + 0) * R4 + lane] = vA;
        o4[(half + 2) * R4 + lane] = vB;
        o4[(half + 4) * R4 + lane] = vC;
    } else {
        float2* o2 = (float2*)outRow;                 // 8B-aligned row
        const int iA = ((half + 0) * R4 + lane) * 2;
        const int iB = ((half + 2) * R4 + lane) * 2;
        const int iC = ((half + 4) * R4 + lane) * 2;
        o2[iA]     = make_float2(vA.x, vA.y);
        o2[iA + 1] = make_float2(vA.z, vA.w);
        o2[iB]     = make_float2(vB.x, vB.y);
        o2[iB + 1] = make_float2(vB.z, vB.w);
        o2[iC]     = make_float2(vC.x, vC.y);
        o2[iC + 1] = make_float2(vC.z, vC.w);
    }

    // Numeric features: 10 floats = 5 float2 (both src and dst 8B-aligned).
    if (t < NUMF / 2) {
        const float2* num2 = (const float2*)(num + (size_t)n * NUMF);
        ((float2*)outRow)[6 * (D_DIM / 2) + t] = num2[t];
    }
}

extern "C" void kernel_launch(void* const* d_in, const int* in_sizes, int n_in,
                              void* d_out, int out_size) {
    const int*   cand = (const int*)d_in[0];
    const float* num  = (const float*)d_in[1];
    const float* blo  = (const float*)d_in[2];
    const float* att  = (const float*)d_in[3];
    float* out = (float*)d_out;

    feature_gather_kernel<<<N_CAND, 256>>>(cand, num, blo, att, out);
}

// round 6
// speedup vs baseline: 1.0332x; 1.0332x over previous
#include <cuda_runtime.h>
#include <cstdint>
#include <cstddef>

// Fixed shapes: B=1, N=1000, T=256, D=512, M=258, NUM=10
// out row = 6*512 + 10 = 3082 floats (12328 B). Row pairs (even,odd) = 24656 B,
// pair start is always 16B-aligned (24656 % 16 == 0).
#define N_CAND   1000
#define T_DIM    256
#define D_DIM    512
#define M_DIM    258
#define NUMF     10
#define ROW_OUT  3082
#define SEC_BYTES (D_DIM * 4)            // 2048
#define PAIR_BYTES (2 * ROW_OUT * 4)     // 24656
#define ROW1_BYTE_OFF (ROW_OUT * 4)      // 12328 (8-mod-16 -> needs smem shift)
#define NUM0_BYTE_OFF (6 * SEC_BYTES)    // 12288
#define NUM1_BYTE_OFF (ROW1_BYTE_OFF + 6 * SEC_BYTES)  // 24616

__device__ __forceinline__ uint32_t smem_u32(const void* p) {
    uint32_t a;
    asm("{ .reg .u64 t; cvta.to.shared.u64 t, %1; cvt.u32.u64 %0, t; }"
        : "=r"(a) : "l"(p));
    return a;
}

__device__ __forceinline__ void bulk_g2s(uint32_t dst_smem, const void* src_gmem,
                                         uint32_t bytes, uint32_t mbar_smem) {
    asm volatile(
        "cp.async.bulk.shared::cluster.global.mbarrier::complete_tx::bytes "
        "[%0], [%1], %2, [%3];"
        :: "r"(dst_smem), "l"(src_gmem), "r"(bytes), "r"(mbar_smem) : "memory");
}

// One block per candidate PAIR. 500 blocks x 128 threads.
__global__ __launch_bounds__(128) void feature_gather_bulk(
    const int* __restrict__ cand,        // [N,6]
    const float* __restrict__ num,       // [N,10]
    const float* __restrict__ blo,       // [N,T,D]
    const float* __restrict__ att,       // [N,M,D]
    float* __restrict__ out)             // [N,3082]
{
    __shared__ __align__(16) unsigned char packed[PAIR_BYTES];      // 24656 B
    __shared__ __align__(16) unsigned char staging[6 * SEC_BYTES];  // 12288 B
    __shared__ __align__(8)  unsigned long long mbar;

    const int t  = threadIdx.x;
    const int n0 = blockIdx.x * 2;
    const int n1 = n0 + 1;

    const uint32_t s_packed  = smem_u32(packed);
    const uint32_t s_staging = smem_u32(staging);
    const uint32_t s_mbar    = smem_u32(&mbar);

    if (t == 0)
        asm volatile("mbarrier.init.shared.b64 [%0], 1;" :: "r"(s_mbar) : "memory");
    __syncthreads();

    if (t == 0) {
        asm volatile("mbarrier.arrive.expect_tx.shared.b64 _, [%0], %1;"
                     :: "r"(s_mbar), "r"(12u * SEC_BYTES) : "memory");

        const int* c0 = cand + n0 * 6;
        const int* c1 = cand + n1 * 6;
        const float* b0 = blo + (size_t)n0 * T_DIM * D_DIM;
        const float* b1 = blo + (size_t)n1 * T_DIM * D_DIM;
        const float* a0 = att + (size_t)n0 * M_DIM * D_DIM;
        const float* a1 = att + (size_t)n1 * M_DIM * D_DIM;

        // Section order: [blo c1, blo c2, blo c4, blo c5, att c0+2, att c3+2]
        const float* src0[6] = {
            b0 + (size_t)c0[1] * D_DIM, b0 + (size_t)c0[2] * D_DIM,
            b0 + (size_t)c0[4] * D_DIM, b0 + (size_t)c0[5] * D_DIM,
            a0 + (size_t)(c0[0] + 2) * D_DIM, a0 + (size_t)(c0[3] + 2) * D_DIM };
        const float* src1[6] = {
            b1 + (size_t)c1[1] * D_DIM, b1 + (size_t)c1[2] * D_DIM,
            b1 + (size_t)c1[4] * D_DIM, b1 + (size_t)c1[5] * D_DIM,
            a1 + (size_t)(c1[0] + 2) * D_DIM, a1 + (size_t)(c1[3] + 2) * D_DIM };

        #pragma unroll
        for (int s = 0; s < 6; s++) {
            // Even row: directly into its packed position (16B-aligned).
            bulk_g2s(s_packed + s * SEC_BYTES, src0[s], SEC_BYTES, s_mbar);
            // Odd row: into aligned staging (packed pos is 8-mod-16).
            bulk_g2s(s_staging + s * SEC_BYTES, src1[s], SEC_BYTES, s_mbar);
        }
    }

    // Numeric features (overlap with bulk loads; disjoint smem regions).
    if (t < 5) {
        float2 v = ((const float2*)(num + (size_t)n0 * NUMF))[t];
        *(float2*)(packed + NUM0_BYTE_OFF + t * 8) = v;
    } else if (t < 10) {
        float2 v = ((const float2*)(num + (size_t)n1 * NUMF))[t - 5];
        *(float2*)(packed + NUM1_BYTE_OFF + (t - 5) * 8) = v;
    }

    // Wait for all 12 bulk loads (phase 0, acquire so LDS sees the data).
    {
        uint32_t done;
        asm volatile(
            "{\n\t"
            ".reg .pred p;\n\t"
            "mbarrier.try_wait.parity.acquire.cta.shared::cta.b64 p, [%1], %2;\n\t"
            "selp.b32 %0, 1, 0, p;\n\t"
            "}"
            : "=r"(done) : "r"(s_mbar), "r"(0u) : "memory");
        if (!done) {
            asm volatile(
                "{\n\t"
                ".reg .pred P1;\n\t"
                "WAIT_LOOP_%=:\n\t"
                "mbarrier.try_wait.parity.acquire.cta.shared::cta.b64 P1, [%0], %1, 0x989680;\n\t"
                "@P1 bra.uni WAIT_DONE_%=;\n\t"
                "bra.uni WAIT_LOOP_%=;\n\t"
                "WAIT_DONE_%=:\n\t"
                "}"
                :: "r"(s_mbar), "r"(0u) : "memory");
        }
    }

    // Shift odd row's sections: staging -> packed row1 positions (8B-aligned).
    // 12288 B = 1536 float2; 128 threads x 12 iterations.
    #pragma unroll
    for (int it = 0; it < 12; it++) {
        const int i = t + it * 128;        // 0..1535
        const int s = i >> 8;              // section 0..5 (256 float2 each)
        const int j = i & 255;
        float2 v = *(const float2*)(staging + (size_t)i * 8);
        *(float2*)(packed + ROW1_BYTE_OFF + s * SEC_BYTES + j * 8) = v;
    }

    __syncthreads();

    if (t == 0) {
        // Order generic smem writes before the async-proxy bulk store read.
        asm volatile("fence.proxy.async.shared::cta;" ::: "memory");
        float* dst = out + (size_t)n0 * ROW_OUT;   // 16B-aligned (pair stride)
        asm volatile(
            "cp.async.bulk.global.shared::cta.bulk_group [%0], [%1], %2;"
            :: "l"(dst), "r"(s_packed), "r"((uint32_t)PAIR_BYTES) : "memory");
        asm volatile("cp.async.bulk.commit_group;" ::: "memory");
        asm volatile("cp.async.bulk.wait_group 0;" ::: "memory");
    }
}

extern "C" void kernel_launch(void* const* d_in, const int* in_sizes, int n_in,
                              void* d_out, int out_size) {
    const int*   cand = (const int*)d_in[0];
    const float* num  = (const float*)d_in[1];
    const float* blo  = (const float*)d_in[2];
    const float* att  = (const float*)d_in[3];
    float* out = (float*)d_out;

    feature_gather_bulk<<<N_CAND / 2, 128>>>(cand, num, blo, att, out);
}